// round 15
// baseline (speedup 1.0000x reference)
#include <cuda_runtime.h>
#include <cuda_fp16.h>
#include <cstdint>

#define N_NODES 100000
#define N_EDGES 3200000
#define F 128
#define NBLK 98            // ceil(N_NODES/1024)

// ---- bit casts --------------------------------------------------------------
__device__ __forceinline__ uint32_t h2u(__half2 h) {
    return *reinterpret_cast<uint32_t*>(&h);
}
__device__ __forceinline__ __half2 u2h(uint32_t u) {
    return *reinterpret_cast<__half2*>(&u);
}

// ---------------- scratch (static device globals; no allocation) -------------
__device__ int      g_is64;
__device__ int      g_csr_src[N_EDGES];
__device__ int      g_deg[N_NODES];          // zero-init at load; re-zeroed by scan1
__device__ int      g_off[N_NODES + 1];
__device__ int      g_cursor[N_NODES];
__device__ int      g_part[128];
__device__ float    g_deginv[N_NODES];
__device__ __align__(16) uint32_t g_x16[(size_t)N_NODES * 64];   // fp16x2 features
__device__ __align__(16) uint32_t g_agg16[(size_t)N_NODES * 64];
__device__ __align__(16) uint32_t g_ha[(size_t)N_NODES * 64];
__device__ __align__(16) uint32_t g_hb[(size_t)N_NODES * 64];
__device__ __align__(16) uint32_t g_w16[6 * 8192];               // fp16 weights

// ---------------- merged prep: dtype probe + convert x + convert w -----------
#define CXB 6250                    // N_NODES*16/256
#define WXB 192                     // 6*8192/256
#define PREP_BLOCKS (CXB + WXB + 1)

__global__ void prep_kernel(const int* __restrict__ w, const float* __restrict__ x,
                            const float* __restrict__ w1l, const float* __restrict__ w1r,
                            const float* __restrict__ w2l, const float* __restrict__ w2r,
                            const float* __restrict__ w3l, const float* __restrict__ w3r) {
    int b = blockIdx.x;
    if (b < CXB) {
        size_t i = (size_t)b * 256 + threadIdx.x;
        if (i < (size_t)N_NODES * 16) {
            float4 a = __ldg(reinterpret_cast<const float4*>(x) + 2 * i);
            float4 c = __ldg(reinterpret_cast<const float4*>(x) + 2 * i + 1);
            uint4 r;
            r.x = h2u(__floats2half2_rn(a.x, a.y));
            r.y = h2u(__floats2half2_rn(a.z, a.w));
            r.z = h2u(__floats2half2_rn(c.x, c.y));
            r.w = h2u(__floats2half2_rn(c.z, c.w));
            reinterpret_cast<uint4*>(g_x16)[i] = r;
        }
    } else if (b < CXB + WXB) {
        int i = (b - CXB) * 256 + threadIdx.x;
        int m = i >> 13, off = i & 8191;
        const float* src = (m == 0) ? w1l : (m == 1) ? w1r : (m == 2) ? w2l
                          : (m == 3) ? w2r : (m == 4) ? w3l : w3r;
        float2 v = reinterpret_cast<const float2*>(src)[off];
        g_w16[i] = h2u(__float22half2_rn(v));
    } else {
        // dtype probe: first 1024 word pairs. int64<2^31 -> odd words all 0.
        if (threadIdx.x == 0) g_is64 = 1;
        __syncthreads();
        int nz = 0;
        #pragma unroll
        for (int k = threadIdx.x; k < 1024; k += 256) nz |= w[2 * k + 1];
        if (nz != 0) g_is64 = 0;
    }
}

__global__ void edge_prep_kernel(const int* __restrict__ w) {
    int e = 2 * (blockIdx.x * blockDim.x + threadIdx.x);
    if (e < N_EDGES) {   // N_EDGES even -> e+1 valid
        int d0, d1;
        if (g_is64) {
            int4 v = *reinterpret_cast<const int4*>(w + 2 * N_EDGES + 2 * e);
            d0 = v.x; d1 = v.z;
        } else {
            int2 v = *reinterpret_cast<const int2*>(w + N_EDGES + e);
            d0 = v.x; d1 = v.y;
        }
        d0 = min(max(d0, 0), N_NODES - 1);
        d1 = min(max(d1, 0), N_NODES - 1);
        atomicAdd(&g_deg[d0], 1);
        atomicAdd(&g_deg[d1], 1);
    }
}

// ---- scan: deg -> off, deginv; scan1 also re-zeroes deg for the next call ---
__global__ void scan1_kernel() {
    __shared__ int wsum[32];
    int b = blockIdx.x, t = threadIdx.x, lane = t & 31, w = t >> 5;
    int i = b * 1024 + t;
    int v = (i < N_NODES) ? g_deg[i] : 0;
    if (i < N_NODES) g_deg[i] = 0;      // leave zeroed for next call
    int x = v;
    #pragma unroll
    for (int d = 1; d < 32; d <<= 1) {
        int y = __shfl_up_sync(0xffffffffu, x, d);
        if (lane >= d) x += y;
    }
    if (lane == 31) wsum[w] = x;
    __syncthreads();
    if (w == 0) {
        int y = wsum[lane];
        #pragma unroll
        for (int d = 1; d < 32; d <<= 1) {
            int z = __shfl_up_sync(0xffffffffu, y, d);
            if (lane >= d) y += z;
        }
        wsum[lane] = y;
    }
    __syncthreads();
    int excl = (x - v) + (w > 0 ? wsum[w - 1] : 0);
    if (i < N_NODES) {
        g_off[i] = excl;
        g_deginv[i] = 1.0f / fmaxf((float)v, 1.0f);
    }
    if (t == 1023) g_part[b] = excl + v;   // raw block total
}

// scan3: each block computes its prefix over g_part serially, offsets slice.
__global__ void scan3_kernel() {
    __shared__ int base_s;
    int b = blockIdx.x, t = threadIdx.x;
    if (t == 0) {
        int base = 0;
        for (int q = 0; q < b; ++q) base += g_part[q];
        base_s = base;
        if (b == NBLK - 1) g_off[N_NODES] = base + g_part[b];
    }
    __syncthreads();
    int i = b * 1024 + t;
    if (i < N_NODES) {
        int o = g_off[i] + base_s;
        g_off[i] = o;
        g_cursor[i] = o;
    }
}

__global__ void csr_fill_kernel(const int* __restrict__ w) {
    int e = 2 * (blockIdx.x * blockDim.x + threadIdx.x);
    if (e < N_EDGES) {
        int s0, s1, d0, d1;
        if (g_is64) {
            int4 sv = *reinterpret_cast<const int4*>(w + 2 * e);
            int4 dv = *reinterpret_cast<const int4*>(w + 2 * N_EDGES + 2 * e);
            s0 = sv.x; s1 = sv.z; d0 = dv.x; d1 = dv.z;
        } else {
            int2 sv = *reinterpret_cast<const int2*>(w + e);
            int2 dv = *reinterpret_cast<const int2*>(w + N_EDGES + e);
            s0 = sv.x; s1 = sv.y; d0 = dv.x; d1 = dv.y;
        }
        s0 = min(max(s0, 0), N_NODES - 1);
        s1 = min(max(s1, 0), N_NODES - 1);
        d0 = min(max(d0, 0), N_NODES - 1);
        d1 = min(max(d1, 0), N_NODES - 1);
        int p0 = atomicAdd(&g_cursor[d0], 1);
        int p1 = atomicAdd(&g_cursor[d1], 1);
        if (p0 >= 0 && p0 < N_EDGES) g_csr_src[p0] = s0;
        if (p1 >= 0 && p1 < N_EDGES) g_csr_src[p1] = s1;
    }
}

// ---------------- aggregation: warp per node, fp16 gather ---------------------
__global__ void agg_kernel(const uint32_t* __restrict__ in, uint32_t* __restrict__ out) {
    int gw   = (blockIdx.x * blockDim.x + threadIdx.x) >> 5;
    int lane = threadIdx.x & 31;
    if (gw >= N_NODES) return;
    int off0 = g_off[gw];
    int off1 = g_off[gw + 1];
    float4 acc = make_float4(0.f, 0.f, 0.f, 0.f);
    const uint2* inv = reinterpret_cast<const uint2*>(in);
    for (int base = off0; base < off1; base += 32) {
        int idx = base + lane;
        int s = (idx < off1) ? g_csr_src[idx] : 0;
        int cnt = min(32, off1 - base);
        #pragma unroll 8
        for (int j = 0; j < cnt; ++j) {
            int sj = __shfl_sync(0xffffffffu, s, j);
            uint2 v = __ldg(inv + (size_t)sj * 32 + lane);   // 4 fp16
            float2 f0 = __half22float2(u2h(v.x));
            float2 f1 = __half22float2(u2h(v.y));
            acc.x += f0.x; acc.y += f0.y; acc.z += f1.x; acc.w += f1.y;
        }
    }
    float dinv = g_deginv[gw];
    uint2 r;
    r.x = h2u(__floats2half2_rn(acc.x * dinv, acc.y * dinv));
    r.y = h2u(__floats2half2_rn(acc.z * dinv, acc.w * dinv));
    reinterpret_cast<uint2*>(out)[(size_t)gw * 32 + lane] = r;
}

// ---------------- fp16 mma.sync GEMM with cp.async tile loads ----------------
#define TS 68
#define SM_BIAS  0
#define SM_WFC   512
#define SM_FCB   1536
#define SM_A     2560
#define SM_W     (SM_A + 128 * TS * 4)          // 2560 + 34816
#define GEMM_SMEM (SM_W + 128 * TS * 4)         // 72192

__device__ __forceinline__ void mma_f16(float* c, uint32_t a0, uint32_t a1, uint32_t a2,
                                        uint32_t a3, uint32_t b0, uint32_t b1) {
    asm volatile(
        "mma.sync.aligned.m16n8k16.row.col.f32.f16.f16.f32 "
        "{%0,%1,%2,%3}, {%4,%5,%6,%7}, {%8,%9}, {%0,%1,%2,%3};"
        : "+f"(c[0]), "+f"(c[1]), "+f"(c[2]), "+f"(c[3])
        : "r"(a0), "r"(a1), "r"(a2), "r"(a3), "r"(b0), "r"(b1));
}

__device__ __forceinline__ void cp16(uint32_t smem_addr, const void* gptr, bool pred) {
    int sz = pred ? 16 : 0;
    asm volatile("cp.async.cg.shared.global [%0], [%1], 16, %2;"
                 :: "r"(smem_addr), "l"(gptr), "r"(sz));
}
#define CP_COMMIT() asm volatile("cp.async.commit_group;")
#define CP_WAIT0()  asm volatile("cp.async.wait_group 0;")

__global__ void __launch_bounds__(256) gemm_mma_kernel(
    const uint32_t* __restrict__ aggi, const uint32_t* __restrict__ xini,
    const uint32_t* __restrict__ wl16, const uint32_t* __restrict__ wr16,
    const float* __restrict__ bias, uint32_t* __restrict__ outh,
    float* __restrict__ outf,
    const float* __restrict__ wfc, const float* __restrict__ bfc, int fc_mode)
{
    extern __shared__ __align__(16) char smem[];
    float*    biasS = reinterpret_cast<float*>(smem + SM_BIAS);
    float*    wfcS  = reinterpret_cast<float*>(smem + SM_WFC);
    float*    fcbuf = reinterpret_cast<float*>(smem + SM_FCB);
    uint32_t* As    = reinterpret_cast<uint32_t*>(smem + SM_A);
    uint32_t* Ws    = reinterpret_cast<uint32_t*>(smem + SM_W);
    uint32_t  As_sa = (uint32_t)__cvta_generic_to_shared(As);
    uint32_t  Ws_sa = (uint32_t)__cvta_generic_to_shared(Ws);

    int t = threadIdx.x, wid = t >> 5, lane = t & 31;
    int g = lane >> 2, q = lane & 3;
    int n0 = blockIdx.x * 128;
    const int row_limit = N_NODES - n0;

    if (t < 128) biasS[t] = bias[t];
    if (t < 256) {
        wfcS[t] = fc_mode ? wfc[t] : 0.f;
        fcbuf[t] = 0.f;
    }

    const int m_off = (wid & 3) * 32;
    const int n_off = (wid >> 2) * 64;

    float acc[2][8][4];
    #pragma unroll
    for (int mi = 0; mi < 2; ++mi)
        #pragma unroll
        for (int ni = 0; ni < 8; ++ni)
            #pragma unroll
            for (int c = 0; c < 4; ++c) acc[mi][ni][c] = 0.f;

    #pragma unroll 1
    for (int chunk = 0; chunk < 2; ++chunk) {
        const uint32_t* Asrc = chunk ? xini : aggi;
        const uint32_t* Wsrc = chunk ? wr16 : wl16;
        __syncthreads();   // previous compute done before smem overwrite
        // A tile via cp.async: each row = 16 × 16B; OOB rows zero-filled (sz=0)
        #pragma unroll
        for (int idx = t; idx < 128 * 16; idx += 256) {
            int r = idx >> 4, c16 = idx & 15;
            bool ok = (r < row_limit);
            int rc = ok ? r : 0;
            cp16(As_sa + (r * TS + c16 * 4) * 4,
                 Asrc + (size_t)(n0 + rc) * 64 + c16 * 4, ok);
        }
        // W tile via cp.async
        #pragma unroll
        for (int idx = t; idx < 128 * 16; idx += 256) {
            int r = idx >> 4, c16 = idx & 15;
            cp16(Ws_sa + (r * TS + c16 * 4) * 4,
                 Wsrc + (size_t)r * 64 + c16 * 4, true);
        }
        CP_COMMIT();
        CP_WAIT0();
        __syncthreads();

        #pragma unroll
        for (int k0 = 0; k0 < 64; k0 += 8) {      // k-pairs: 8 per m16n8k16 step
            uint32_t bf[8][2];
            #pragma unroll
            for (int ni = 0; ni < 8; ++ni) {
                const uint32_t* wp = Ws + (n_off + ni * 8 + g) * TS + k0 + q;
                bf[ni][0] = wp[0];
                bf[ni][1] = wp[4];
            }
            #pragma unroll
            for (int mi = 0; mi < 2; ++mi) {
                const uint32_t* ap = As + (m_off + mi * 16 + g) * TS + k0 + q;
                uint32_t a0 = ap[0];
                uint32_t a1 = ap[8 * TS];
                uint32_t a2 = ap[4];
                uint32_t a3 = ap[8 * TS + 4];
                #pragma unroll
                for (int ni = 0; ni < 8; ++ni)
                    mma_f16(acc[mi][ni], a0, a1, a2, a3, bf[ni][0], bf[ni][1]);
            }
        }
    }

    // epilogue: bias + relu -> fp16 h store, or fused fc
    #pragma unroll
    for (int mi = 0; mi < 2; ++mi) {
        #pragma unroll
        for (int rr = 0; rr < 2; ++rr) {
            int row = m_off + mi * 16 + g + rr * 8;
            int node = n0 + row;
            float rfc0 = 0.f, rfc1 = 0.f;
            #pragma unroll
            for (int ni = 0; ni < 8; ++ni) {
                int col = n_off + ni * 8 + q * 2;
                float h0 = fmaxf(acc[mi][ni][rr * 2 + 0] + biasS[col], 0.f);
                float h1 = fmaxf(acc[mi][ni][rr * 2 + 1] + biasS[col + 1], 0.f);
                if (!fc_mode) {
                    if (node < N_NODES)
                        outh[(size_t)node * 64 + (col >> 1)] =
                            h2u(__floats2half2_rn(h0, h1));
                } else {
                    rfc0 += h0 * wfcS[col] + h1 * wfcS[col + 1];
                    rfc1 += h0 * wfcS[128 + col] + h1 * wfcS[128 + col + 1];
                }
            }
            if (fc_mode) {
                #pragma unroll
                for (int o = 1; o < 4; o <<= 1) {
                    rfc0 += __shfl_xor_sync(0xffffffffu, rfc0, o);
                    rfc1 += __shfl_xor_sync(0xffffffffu, rfc1, o);
                }
                if (q == 0) {
                    atomicAdd(&fcbuf[row * 2 + 0], rfc0);
                    atomicAdd(&fcbuf[row * 2 + 1], rfc1);
                }
            }
        }
    }
    if (fc_mode) {
        __syncthreads();
        if (t < 256) {
            int row = t >> 1, o = t & 1;
            int node = n0 + row;
            if (node < N_NODES)
                outf[(size_t)node * 2 + o] = fcbuf[t] + __ldg(&bfc[o]);
        }
    }
}

// ---------------- launch ------------------------------------------------------
extern "C" void kernel_launch(void* const* d_in, const int* in_sizes, int n_in,
                              void* d_out, int out_size) {
    const float* x   = (const float*)d_in[0];
    const int*   ei  = (const int*)d_in[1];
    const float* w1l = (const float*)d_in[2];
    const float* b1  = (const float*)d_in[3];
    const float* w1r = (const float*)d_in[4];
    const float* w2l = (const float*)d_in[5];
    const float* b2  = (const float*)d_in[6];
    const float* w2r = (const float*)d_in[7];
    const float* w3l = (const float*)d_in[8];
    const float* b3  = (const float*)d_in[9];
    const float* w3r = (const float*)d_in[10];
    const float* wfc = (const float*)d_in[11];
    const float* bfc = (const float*)d_in[12];
    float* out = (float*)d_out;

    uint32_t *x16, *agg16, *ha, *hb, *w16;
    cudaGetSymbolAddress((void**)&x16,   g_x16);
    cudaGetSymbolAddress((void**)&agg16, g_agg16);
    cudaGetSymbolAddress((void**)&ha,    g_ha);
    cudaGetSymbolAddress((void**)&hb,    g_hb);
    cudaGetSymbolAddress((void**)&w16,   g_w16);

    cudaFuncSetAttribute(gemm_mma_kernel, cudaFuncAttributeMaxDynamicSharedMemorySize, GEMM_SMEM);

    const int EB2 = (N_EDGES / 2 + 255) / 256;     // 2 edges per thread
    const int WB  = (N_NODES * 32 + 255) / 256;
    const int GB  = (N_NODES + 127) / 128;

    prep_kernel<<<PREP_BLOCKS, 256>>>(ei, x, w1l, w1r, w2l, w2r, w3l, w3r);
    edge_prep_kernel<<<EB2, 256>>>(ei);
    scan1_kernel<<<NBLK, 1024>>>();
    scan3_kernel<<<NBLK, 1024>>>();
    csr_fill_kernel<<<EB2, 256>>>(ei);

    // layer 1
    agg_kernel<<<WB, 256>>>(x16, agg16);
    gemm_mma_kernel<<<GB, 256, GEMM_SMEM>>>(agg16, x16, w16 + 0 * 8192, w16 + 1 * 8192,
                                            b1, ha, out, wfc, bfc, 0);
    // layer 2
    agg_kernel<<<WB, 256>>>(ha, agg16);
    gemm_mma_kernel<<<GB, 256, GEMM_SMEM>>>(agg16, ha, w16 + 2 * 8192, w16 + 3 * 8192,
                                            b2, hb, out, wfc, bfc, 0);
    // layer 3 + fused fc
    agg_kernel<<<WB, 256>>>(hb, agg16);
    gemm_mma_kernel<<<GB, 256, GEMM_SMEM>>>(agg16, hb, w16 + 4 * 8192, w16 + 5 * 8192,
                                            b3, ha, out, wfc, bfc, 1);
}

// round 16
// speedup vs baseline: 1.0108x; 1.0108x over previous
#include <cuda_runtime.h>
#include <cuda_fp16.h>
#include <cstdint>

#define N_NODES 100000
#define N_EDGES 3200000
#define F 128
#define NBLK 98            // ceil(N_NODES/1024)

// ---- bit casts --------------------------------------------------------------
__device__ __forceinline__ uint32_t h2u(__half2 h) {
    return *reinterpret_cast<uint32_t*>(&h);
}
__device__ __forceinline__ __half2 u2h(uint32_t u) {
    return *reinterpret_cast<__half2*>(&u);
}

// ---------------- scratch (static device globals; no allocation) -------------
__device__ int      g_is64;
__device__ int      g_csr_src[N_EDGES];
__device__ int      g_deg[N_NODES];          // zero-init at load; re-zeroed by scan1
__device__ int      g_off[N_NODES + 1];
__device__ int      g_cursor[N_NODES];
__device__ int      g_part[128];
__device__ float    g_deginv[N_NODES];
__device__ __align__(16) uint32_t g_x16[(size_t)N_NODES * 64];   // fp16x2 features
__device__ __align__(16) uint32_t g_agg16[(size_t)N_NODES * 64];
__device__ __align__(16) uint32_t g_ha[(size_t)N_NODES * 64];
__device__ __align__(16) uint32_t g_hb[(size_t)N_NODES * 64];
__device__ __align__(16) uint32_t g_w16[6 * 8192];               // fp16 weights

// ------- merged prep: edge-degree count + dtype probe + convert x + w --------
// Partitions (in scheduling order): edge blocks first (longest pole), then
// convert_x, convert_w, and the global dtype-probe block (for csr_fill).
#define EPB 6250                    // ceil(N_EDGES/2/256), 2 edges per thread
#define CXB 6250                    // N_NODES*16/256
#define WXB 192                     // 6*8192/256
#define PREP_BLOCKS (EPB + CXB + WXB + 1)

__global__ void prep_kernel(const int* __restrict__ w, const float* __restrict__ x,
                            const float* __restrict__ w1l, const float* __restrict__ w1r,
                            const float* __restrict__ w2l, const float* __restrict__ w2r,
                            const float* __restrict__ w3l, const float* __restrict__ w3r) {
    int b = blockIdx.x;
    if (b < EPB) {
        // per-warp dtype self-probe: first 32 word-pairs. int64<2^31 -> odd
        // words all zero; int32 -> random node ids (all-zero prob ~1e-160).
        int odd = w[2 * (threadIdx.x & 31) + 1];
        unsigned any = __ballot_sync(0xffffffffu, odd != 0);
        bool is64 = (any == 0u);

        int e = 2 * (b * 256 + threadIdx.x);
        if (e < N_EDGES) {   // N_EDGES even -> e+1 valid
            int d0, d1;
            if (is64) {
                int4 v = *reinterpret_cast<const int4*>(w + 2 * N_EDGES + 2 * e);
                d0 = v.x; d1 = v.z;
            } else {
                int2 v = *reinterpret_cast<const int2*>(w + N_EDGES + e);
                d0 = v.x; d1 = v.y;
            }
            d0 = min(max(d0, 0), N_NODES - 1);
            d1 = min(max(d1, 0), N_NODES - 1);
            atomicAdd(&g_deg[d0], 1);
            atomicAdd(&g_deg[d1], 1);
        }
    } else if (b < EPB + CXB) {
        size_t i = (size_t)(b - EPB) * 256 + threadIdx.x;
        if (i < (size_t)N_NODES * 16) {
            float4 a = __ldg(reinterpret_cast<const float4*>(x) + 2 * i);
            float4 c = __ldg(reinterpret_cast<const float4*>(x) + 2 * i + 1);
            uint4 r;
            r.x = h2u(__floats2half2_rn(a.x, a.y));
            r.y = h2u(__floats2half2_rn(a.z, a.w));
            r.z = h2u(__floats2half2_rn(c.x, c.y));
            r.w = h2u(__floats2half2_rn(c.z, c.w));
            reinterpret_cast<uint4*>(g_x16)[i] = r;
        }
    } else if (b < EPB + CXB + WXB) {
        int i = (b - EPB - CXB) * 256 + threadIdx.x;
        int m = i >> 13, off = i & 8191;
        const float* src = (m == 0) ? w1l : (m == 1) ? w1r : (m == 2) ? w2l
                          : (m == 3) ? w2r : (m == 4) ? w3l : w3r;
        float2 v = reinterpret_cast<const float2*>(src)[off];
        g_w16[i] = h2u(__float22half2_rn(v));
    } else {
        // global dtype probe (for csr_fill): first 1024 word pairs.
        if (threadIdx.x == 0) g_is64 = 1;
        __syncthreads();
        int nz = 0;
        #pragma unroll
        for (int k = threadIdx.x; k < 1024; k += 256) nz |= w[2 * k + 1];
        if (nz != 0) g_is64 = 0;
    }
}

// ---- scan: deg -> off, deginv; scan1 also re-zeroes deg for the next call ---
__global__ void scan1_kernel() {
    __shared__ int wsum[32];
    int b = blockIdx.x, t = threadIdx.x, lane = t & 31, w = t >> 5;
    int i = b * 1024 + t;
    int v = (i < N_NODES) ? g_deg[i] : 0;
    if (i < N_NODES) g_deg[i] = 0;      // leave zeroed for next call
    int x = v;
    #pragma unroll
    for (int d = 1; d < 32; d <<= 1) {
        int y = __shfl_up_sync(0xffffffffu, x, d);
        if (lane >= d) x += y;
    }
    if (lane == 31) wsum[w] = x;
    __syncthreads();
    if (w == 0) {
        int y = wsum[lane];
        #pragma unroll
        for (int d = 1; d < 32; d <<= 1) {
            int z = __shfl_up_sync(0xffffffffu, y, d);
            if (lane >= d) y += z;
        }
        wsum[lane] = y;
    }
    __syncthreads();
    int excl = (x - v) + (w > 0 ? wsum[w - 1] : 0);
    if (i < N_NODES) {
        g_off[i] = excl;
        g_deginv[i] = 1.0f / fmaxf((float)v, 1.0f);
    }
    if (t == 1023) g_part[b] = excl + v;   // raw block total
}

// scan3: each block computes its prefix over g_part serially, offsets slice.
__global__ void scan3_kernel() {
    __shared__ int base_s;
    int b = blockIdx.x, t = threadIdx.x;
    if (t == 0) {
        int base = 0;
        for (int q = 0; q < b; ++q) base += g_part[q];
        base_s = base;
        if (b == NBLK - 1) g_off[N_NODES] = base + g_part[b];
    }
    __syncthreads();
    int i = b * 1024 + t;
    if (i < N_NODES) {
        int o = g_off[i] + base_s;
        g_off[i] = o;
        g_cursor[i] = o;
    }
}

__global__ void csr_fill_kernel(const int* __restrict__ w) {
    int e = 2 * (blockIdx.x * blockDim.x + threadIdx.x);
    if (e < N_EDGES) {
        int s0, s1, d0, d1;
        if (g_is64) {
            int4 sv = *reinterpret_cast<const int4*>(w + 2 * e);
            int4 dv = *reinterpret_cast<const int4*>(w + 2 * N_EDGES + 2 * e);
            s0 = sv.x; s1 = sv.z; d0 = dv.x; d1 = dv.z;
        } else {
            int2 sv = *reinterpret_cast<const int2*>(w + e);
            int2 dv = *reinterpret_cast<const int2*>(w + N_EDGES + e);
            s0 = sv.x; s1 = sv.y; d0 = dv.x; d1 = dv.y;
        }
        s0 = min(max(s0, 0), N_NODES - 1);
        s1 = min(max(s1, 0), N_NODES - 1);
        d0 = min(max(d0, 0), N_NODES - 1);
        d1 = min(max(d1, 0), N_NODES - 1);
        int p0 = atomicAdd(&g_cursor[d0], 1);
        int p1 = atomicAdd(&g_cursor[d1], 1);
        if (p0 >= 0 && p0 < N_EDGES) g_csr_src[p0] = s0;
        if (p1 >= 0 && p1 < N_EDGES) g_csr_src[p1] = s1;
    }
}

// ---------------- aggregation: warp per node, fp16 gather ---------------------
__global__ void agg_kernel(const uint32_t* __restrict__ in, uint32_t* __restrict__ out) {
    int gw   = (blockIdx.x * blockDim.x + threadIdx.x) >> 5;
    int lane = threadIdx.x & 31;
    if (gw >= N_NODES) return;
    int off0 = g_off[gw];
    int off1 = g_off[gw + 1];
    float4 acc = make_float4(0.f, 0.f, 0.f, 0.f);
    const uint2* inv = reinterpret_cast<const uint2*>(in);
    for (int base = off0; base < off1; base += 32) {
        int idx = base + lane;
        int s = (idx < off1) ? g_csr_src[idx] : 0;
        int cnt = min(32, off1 - base);
        #pragma unroll 8
        for (int j = 0; j < cnt; ++j) {
            int sj = __shfl_sync(0xffffffffu, s, j);
            uint2 v = __ldg(inv + (size_t)sj * 32 + lane);   // 4 fp16
            float2 f0 = __half22float2(u2h(v.x));
            float2 f1 = __half22float2(u2h(v.y));
            acc.x += f0.x; acc.y += f0.y; acc.z += f1.x; acc.w += f1.y;
        }
    }
    float dinv = g_deginv[gw];
    uint2 r;
    r.x = h2u(__floats2half2_rn(acc.x * dinv, acc.y * dinv));
    r.y = h2u(__floats2half2_rn(acc.z * dinv, acc.w * dinv));
    reinterpret_cast<uint2*>(out)[(size_t)gw * 32 + lane] = r;
}

// ---------------- fp16 mma.sync GEMM with cp.async tile loads ----------------
#define TS 68
#define SM_BIAS  0
#define SM_WFC   512
#define SM_FCB   1536
#define SM_A     2560
#define SM_W     (SM_A + 128 * TS * 4)          // 2560 + 34816
#define GEMM_SMEM (SM_W + 128 * TS * 4)         // 72192

__device__ __forceinline__ void mma_f16(float* c, uint32_t a0, uint32_t a1, uint32_t a2,
                                        uint32_t a3, uint32_t b0, uint32_t b1) {
    asm volatile(
        "mma.sync.aligned.m16n8k16.row.col.f32.f16.f16.f32 "
        "{%0,%1,%2,%3}, {%4,%5,%6,%7}, {%8,%9}, {%0,%1,%2,%3};"
        : "+f"(c[0]), "+f"(c[1]), "+f"(c[2]), "+f"(c[3])
        : "r"(a0), "r"(a1), "r"(a2), "r"(a3), "r"(b0), "r"(b1));
}

__device__ __forceinline__ void cp16(uint32_t smem_addr, const void* gptr, bool pred) {
    int sz = pred ? 16 : 0;
    asm volatile("cp.async.cg.shared.global [%0], [%1], 16, %2;"
                 :: "r"(smem_addr), "l"(gptr), "r"(sz));
}
#define CP_COMMIT() asm volatile("cp.async.commit_group;")
#define CP_WAIT0()  asm volatile("cp.async.wait_group 0;")

__global__ void __launch_bounds__(256) gemm_mma_kernel(
    const uint32_t* __restrict__ aggi, const uint32_t* __restrict__ xini,
    const uint32_t* __restrict__ wl16, const uint32_t* __restrict__ wr16,
    const float* __restrict__ bias, uint32_t* __restrict__ outh,
    float* __restrict__ outf,
    const float* __restrict__ wfc, const float* __restrict__ bfc, int fc_mode)
{
    extern __shared__ __align__(16) char smem[];
    float*    biasS = reinterpret_cast<float*>(smem + SM_BIAS);
    float*    wfcS  = reinterpret_cast<float*>(smem + SM_WFC);
    float*    fcbuf = reinterpret_cast<float*>(smem + SM_FCB);
    uint32_t* As    = reinterpret_cast<uint32_t*>(smem + SM_A);
    uint32_t* Ws    = reinterpret_cast<uint32_t*>(smem + SM_W);
    uint32_t  As_sa = (uint32_t)__cvta_generic_to_shared(As);
    uint32_t  Ws_sa = (uint32_t)__cvta_generic_to_shared(Ws);

    int t = threadIdx.x, wid = t >> 5, lane = t & 31;
    int g = lane >> 2, q = lane & 3;
    int n0 = blockIdx.x * 128;
    const int row_limit = N_NODES - n0;

    if (t < 128) biasS[t] = bias[t];
    if (t < 256) {
        wfcS[t] = fc_mode ? wfc[t] : 0.f;
        fcbuf[t] = 0.f;
    }

    const int m_off = (wid & 3) * 32;
    const int n_off = (wid >> 2) * 64;

    float acc[2][8][4];
    #pragma unroll
    for (int mi = 0; mi < 2; ++mi)
        #pragma unroll
        for (int ni = 0; ni < 8; ++ni)
            #pragma unroll
            for (int c = 0; c < 4; ++c) acc[mi][ni][c] = 0.f;

    #pragma unroll 1
    for (int chunk = 0; chunk < 2; ++chunk) {
        const uint32_t* Asrc = chunk ? xini : aggi;
        const uint32_t* Wsrc = chunk ? wr16 : wl16;
        __syncthreads();   // previous compute done before smem overwrite
        // A tile via cp.async: each row = 16 × 16B; OOB rows zero-filled (sz=0)
        #pragma unroll
        for (int idx = t; idx < 128 * 16; idx += 256) {
            int r = idx >> 4, c16 = idx & 15;
            bool ok = (r < row_limit);
            int rc = ok ? r : 0;
            cp16(As_sa + (r * TS + c16 * 4) * 4,
                 Asrc + (size_t)(n0 + rc) * 64 + c16 * 4, ok);
        }
        // W tile via cp.async
        #pragma unroll
        for (int idx = t; idx < 128 * 16; idx += 256) {
            int r = idx >> 4, c16 = idx & 15;
            cp16(Ws_sa + (r * TS + c16 * 4) * 4,
                 Wsrc + (size_t)r * 64 + c16 * 4, true);
        }
        CP_COMMIT();
        CP_WAIT0();
        __syncthreads();

        #pragma unroll
        for (int k0 = 0; k0 < 64; k0 += 8) {      // k-pairs: 8 per m16n8k16 step
            uint32_t bf[8][2];
            #pragma unroll
            for (int ni = 0; ni < 8; ++ni) {
                const uint32_t* wp = Ws + (n_off + ni * 8 + g) * TS + k0 + q;
                bf[ni][0] = wp[0];
                bf[ni][1] = wp[4];
            }
            #pragma unroll
            for (int mi = 0; mi < 2; ++mi) {
                const uint32_t* ap = As + (m_off + mi * 16 + g) * TS + k0 + q;
                uint32_t a0 = ap[0];
                uint32_t a1 = ap[8 * TS];
                uint32_t a2 = ap[4];
                uint32_t a3 = ap[8 * TS + 4];
                #pragma unroll
                for (int ni = 0; ni < 8; ++ni)
                    mma_f16(acc[mi][ni], a0, a1, a2, a3, bf[ni][0], bf[ni][1]);
            }
        }
    }

    // epilogue: bias + relu -> fp16 h store, or fused fc
    #pragma unroll
    for (int mi = 0; mi < 2; ++mi) {
        #pragma unroll
        for (int rr = 0; rr < 2; ++rr) {
            int row = m_off + mi * 16 + g + rr * 8;
            int node = n0 + row;
            float rfc0 = 0.f, rfc1 = 0.f;
            #pragma unroll
            for (int ni = 0; ni < 8; ++ni) {
                int col = n_off + ni * 8 + q * 2;
                float h0 = fmaxf(acc[mi][ni][rr * 2 + 0] + biasS[col], 0.f);
                float h1 = fmaxf(acc[mi][ni][rr * 2 + 1] + biasS[col + 1], 0.f);
                if (!fc_mode) {
                    if (node < N_NODES)
                        outh[(size_t)node * 64 + (col >> 1)] =
                            h2u(__floats2half2_rn(h0, h1));
                } else {
                    rfc0 += h0 * wfcS[col] + h1 * wfcS[col + 1];
                    rfc1 += h0 * wfcS[128 + col] + h1 * wfcS[128 + col + 1];
                }
            }
            if (fc_mode) {
                #pragma unroll
                for (int o = 1; o < 4; o <<= 1) {
                    rfc0 += __shfl_xor_sync(0xffffffffu, rfc0, o);
                    rfc1 += __shfl_xor_sync(0xffffffffu, rfc1, o);
                }
                if (q == 0) {
                    atomicAdd(&fcbuf[row * 2 + 0], rfc0);
                    atomicAdd(&fcbuf[row * 2 + 1], rfc1);
                }
            }
        }
    }
    if (fc_mode) {
        __syncthreads();
        if (t < 256) {
            int row = t >> 1, o = t & 1;
            int node = n0 + row;
            if (node < N_NODES)
                outf[(size_t)node * 2 + o] = fcbuf[t] + __ldg(&bfc[o]);
        }
    }
}

// ---------------- launch ------------------------------------------------------
extern "C" void kernel_launch(void* const* d_in, const int* in_sizes, int n_in,
                              void* d_out, int out_size) {
    const float* x   = (const float*)d_in[0];
    const int*   ei  = (const int*)d_in[1];
    const float* w1l = (const float*)d_in[2];
    const float* b1  = (const float*)d_in[3];
    const float* w1r = (const float*)d_in[4];
    const float* w2l = (const float*)d_in[5];
    const float* b2  = (const float*)d_in[6];
    const float* w2r = (const float*)d_in[7];
    const float* w3l = (const float*)d_in[8];
    const float* b3  = (const float*)d_in[9];
    const float* w3r = (const float*)d_in[10];
    const float* wfc = (const float*)d_in[11];
    const float* bfc = (const float*)d_in[12];
    float* out = (float*)d_out;

    uint32_t *x16, *agg16, *ha, *hb, *w16;
    cudaGetSymbolAddress((void**)&x16,   g_x16);
    cudaGetSymbolAddress((void**)&agg16, g_agg16);
    cudaGetSymbolAddress((void**)&ha,    g_ha);
    cudaGetSymbolAddress((void**)&hb,    g_hb);
    cudaGetSymbolAddress((void**)&w16,   g_w16);

    cudaFuncSetAttribute(gemm_mma_kernel, cudaFuncAttributeMaxDynamicSharedMemorySize, GEMM_SMEM);

    const int EB2 = (N_EDGES / 2 + 255) / 256;     // 2 edges per thread
    const int WB  = (N_NODES * 32 + 255) / 256;
    const int GB  = (N_NODES + 127) / 128;

    prep_kernel<<<PREP_BLOCKS, 256>>>(ei, x, w1l, w1r, w2l, w2r, w3l, w3r);
    scan1_kernel<<<NBLK, 1024>>>();
    scan3_kernel<<<NBLK, 1024>>>();
    csr_fill_kernel<<<EB2, 256>>>(ei);

    // layer 1
    agg_kernel<<<WB, 256>>>(x16, agg16);
    gemm_mma_kernel<<<GB, 256, GEMM_SMEM>>>(agg16, x16, w16 + 0 * 8192, w16 + 1 * 8192,
                                            b1, ha, out, wfc, bfc, 0);
    // layer 2
    agg_kernel<<<WB, 256>>>(ha, agg16);
    gemm_mma_kernel<<<GB, 256, GEMM_SMEM>>>(agg16, ha, w16 + 2 * 8192, w16 + 3 * 8192,
                                            b2, hb, out, wfc, bfc, 0);
    // layer 3 + fused fc
    agg_kernel<<<WB, 256>>>(hb, agg16);
    gemm_mma_kernel<<<GB, 256, GEMM_SMEM>>>(agg16, hb, w16 + 4 * 8192, w16 + 5 * 8192,
                                            b3, ha, out, wfc, bfc, 1);
}